// round 6
// baseline (speedup 1.0000x reference)
#include <cuda_runtime.h>
#include <cuda_bf16.h>
#include <cstdint>

#define BN_EPS 1e-5f

// ---------------- scratch (no allocations allowed) ----------------
__device__ float g_x1[200000 * 64];        // conv1 output (N x 64)
__device__ float g_x2[(32768 + 1) * 128];  // conv2 output (M x 128)
__device__ float g_stats[512];             // [sum | sumsq | a | d]

// ---------------- helpers ----------------
static __device__ __forceinline__ void red_add2(float* p, float a, float b) {
    asm volatile("red.global.add.v2.f32 [%0], {%1,%2};"
                 :: "l"(p), "f"(a), "f"(b) : "memory");
}
static __device__ __forceinline__ void mma_bf16(float* d, uint32_t a0, uint32_t a1,
                                                uint32_t a2, uint32_t a3,
                                                uint32_t b0, uint32_t b1) {
    asm volatile(
        "mma.sync.aligned.m16n8k16.row.col.f32.bf16.bf16.f32 "
        "{%0,%1,%2,%3}, {%4,%5,%6,%7}, {%8,%9}, {%0,%1,%2,%3};"
        : "+f"(d[0]), "+f"(d[1]), "+f"(d[2]), "+f"(d[3])
        : "r"(a0), "r"(a1), "r"(a2), "r"(a3), "r"(b0), "r"(b1));
}
static __device__ __forceinline__ void ldsm4(uint32_t& r0, uint32_t& r1,
                                             uint32_t& r2, uint32_t& r3, uint32_t a) {
    asm volatile("ldmatrix.sync.aligned.m8n8.x4.shared.b16 {%0,%1,%2,%3}, [%4];"
                 : "=r"(r0), "=r"(r1), "=r"(r2), "=r"(r3) : "r"(a));
}
static __device__ __forceinline__ uint32_t smem_off(const void* p) {
    return (uint32_t)__cvta_generic_to_shared(p);
}

// ============================================================================
// Sparse conv: gather + bf16 split -> warp mma.sync (3-term) -> red scatter.
// Grid (X, 27). NW warps (8*WN); warp (wm, wn): rows wm*16..+15, n-tiles
// wn*NTW..+NTW-1. A smem [128][2*CIN+8] bf16 (hi|lo); B smem [COUT][2*CIN+8]
// = W^T (hi|lo). D = Ah*Bh + Ah*Bl + Al*Bh, fp32 accum. Fragments via
// ldmatrix.x4. Pad rows gather row 0 (in-bounds); never scattered.
// ============================================================================
template <int CIN, int COUT, int WN>
__global__ __launch_bounds__(WN * 256)
void conv_mma(const float* __restrict__ fin, const float* __restrict__ W,
              const int* __restrict__ rin, const int* __restrict__ rout,
              float* __restrict__ out, int P, int n_in) {
    constexpr int NW = 8 * WN;            // warps
    constexpr int NTHR = NW * 32;
    constexpr int SA = 2 * CIN + 8;       // bf16 row stride (272B/528B: bank-clean)
    constexpr int NTW = COUT / 8 / WN;    // n8-tiles per warp (even)
    constexpr int KS = CIN / 16;          // k16 steps per term

    const int k = blockIdx.y;
    const int rbase = k * P;
    // liveness probe: pads trail within an offset; this block's first tile dead
    // => all its tiles dead. Exit before touching W.
    if ((blockIdx.x << 7) >= P) return;
    if (rin[rbase + (blockIdx.x << 7)] == n_in) return;

    extern __shared__ __nv_bfloat16 smem_bf[];
    __nv_bfloat16* As = smem_bf;              // 128 * SA
    __nv_bfloat16* Bs = smem_bf + 128 * SA;   // COUT * SA
    __shared__ int s_in[128], s_out[128];

    const int tid = threadIdx.x;

    // ---- W_k -> Bs (hi | lo), once per block ----
    const float* Wk = W + (size_t)k * CIN * COUT;
    for (int idx = tid; idx < CIN * COUT; idx += NTHR) {
        int cin = idx / COUT, cout = idx - cin * COUT;
        float w = Wk[idx];
        __nv_bfloat16 h = __float2bfloat16(w);
        __nv_bfloat16 l = __float2bfloat16(w - __bfloat162float(h));
        Bs[cout * SA + cin] = h;
        Bs[cout * SA + CIN + cin] = l;
    }

    const int lane = tid & 31, wid = tid >> 5;
    const int wm = wid & 7, wn = wid >> 3;
    const int wp0 = wm * 16;
    const int n0 = wn * (NTW * 8);
    const int g = lane >> 2, q = lane & 3;
    // ldmatrix per-lane bases (byte smem offsets)
    const int T = lane >> 3, r8 = lane & 7;
    const uint32_t aBase = smem_off(As) +
        (uint32_t)(((wp0 + r8 + 8 * (T & 1)) * SA + 8 * (T >> 1)) * 2);
    const uint32_t bBase = smem_off(Bs) +
        (uint32_t)(((n0 + r8 + 8 * (T >> 1)) * SA + 8 * (T & 1)) * 2);

    constexpr int TPR = NW / 4;           // gather threads per pair-row
    constexpr int CHUNK = CIN / TPR;      // floats per gather thread
    const int ntiles = (P + 127) >> 7;

    for (int t = blockIdx.x; t < ntiles; t += gridDim.x) {
        if (tid < 128) {
            int idx = (t << 7) + tid;
            s_in[tid] = (idx < P) ? rin[rbase + idx] : n_in;
            s_out[tid] = (idx < P) ? rout[rbase + idx] : 0;
        }
        __syncthreads();
        if (s_in[0] == n_in) break;       // pads trail: no more live tiles

        // ---- gather + bf16 split (clamped row; always in-bounds) ----
        {
            int row = tid / TPR, part = tid % TPR;
            int src_row = s_in[row];
            if (src_row == n_in) src_row = 0;
            const float4* src =
                (const float4*)(fin + (size_t)src_row * CIN + part * CHUNK);
            __nv_bfloat16* da = As + row * SA + part * CHUNK;
#pragma unroll
            for (int j = 0; j < CHUNK / 4; j++) {
                float4 vv = src[j];
                __nv_bfloat16 hx = __float2bfloat16(vv.x), hy = __float2bfloat16(vv.y);
                __nv_bfloat16 hz = __float2bfloat16(vv.z), hw = __float2bfloat16(vv.w);
                __nv_bfloat162 h01 = __halves2bfloat162(hx, hy);
                __nv_bfloat162 h23 = __halves2bfloat162(hz, hw);
                __nv_bfloat162 l01 = __halves2bfloat162(
                    __float2bfloat16(vv.x - __bfloat162float(hx)),
                    __float2bfloat16(vv.y - __bfloat162float(hy)));
                __nv_bfloat162 l23 = __halves2bfloat162(
                    __float2bfloat16(vv.z - __bfloat162float(hz)),
                    __float2bfloat16(vv.w - __bfloat162float(hw)));
                *(uint2*)(da + 4 * j) = make_uint2(*(uint32_t*)&h01, *(uint32_t*)&h23);
                *(uint2*)(da + CIN + 4 * j) = make_uint2(*(uint32_t*)&l01, *(uint32_t*)&l23);
            }
        }
        __syncthreads();

        // ---- MMA: 3 terms x KS k-steps x NTW n-tiles, ldmatrix fragments ----
        float d[NTW][4];
#pragma unroll
        for (int n = 0; n < NTW; n++) {
            d[n][0] = 0.f; d[n][1] = 0.f; d[n][2] = 0.f; d[n][3] = 0.f;
        }
#pragma unroll
        for (int term = 0; term < 3; term++) {
            const int ka0 = (term == 2) ? CIN : 0;
            const int kb0 = (term == 1) ? CIN : 0;
#pragma unroll
            for (int s = 0; s < KS; s++) {
                uint32_t a0, a1, a2, a3;
                ldsm4(a0, a1, a2, a3, aBase + (uint32_t)((ka0 + s * 16) * 2));
                uint32_t bA = bBase + (uint32_t)((kb0 + s * 16) * 2);
#pragma unroll
                for (int jj = 0; jj < NTW / 2; jj++) {
                    uint32_t b0, b1, b2, b3;
                    ldsm4(b0, b1, b2, b3, bA);
                    mma_bf16(d[2 * jj], a0, a1, a2, a3, b0, b1);
                    mma_bf16(d[2 * jj + 1], a0, a1, a2, a3, b2, b3);
                    bA += 16 * SA * 2;
                }
            }
        }

        // ---- scatter: rows wp0+g, wp0+g+8; cols n0 + j*8 + q*2 ----
        {
            int r0 = wp0 + g, r1 = r0 + 8;
            bool v0 = (s_in[r0] != n_in), v1 = (s_in[r1] != n_in);
            float* dst0 = out + (size_t)s_out[r0] * COUT + n0 + q * 2;
            float* dst1 = out + (size_t)s_out[r1] * COUT + n0 + q * 2;
#pragma unroll
            for (int j = 0; j < NTW; j++) {
                if (v0) red_add2(dst0 + j * 8, d[j][0], d[j][1]);
                if (v1) red_add2(dst1 + j * 8, d[j][2], d[j][3]);
            }
        }
        __syncthreads();
    }
}

// ---------------- BatchNorm (training stats) + ReLU ----------------
template <int COUT>
__global__ void bn_stats(const float* __restrict__ x, int R, float* __restrict__ st) {
    __shared__ float ss[COUT], sq[COUT];
    int tid = threadIdx.x;
    if (tid < COUT) { ss[tid] = 0.f; sq[tid] = 0.f; }
    __syncthreads();
    int c = tid & (COUT - 1);
    constexpr int RPB = 256 / COUT;
    float s = 0.f, qq = 0.f;
    for (int r = blockIdx.x * RPB + tid / COUT; r < R; r += gridDim.x * RPB) {
        float v = x[(size_t)r * COUT + c];
        s += v;
        qq += v * v;
    }
    atomicAdd(&ss[c], s);
    atomicAdd(&sq[c], qq);
    __syncthreads();
    if (tid < COUT) {
        atomicAdd(&st[tid], ss[tid]);
        atomicAdd(&st[COUT + tid], sq[tid]);
    }
}

template <int COUT>
__global__ void bn_finalize(const float* __restrict__ g, const float* __restrict__ b,
                            float invR, float* __restrict__ st) {
    int c = threadIdx.x;
    if (c < COUT) {
        float mu = st[c] * invR;
        float var = st[COUT + c] * invR - mu * mu;
        float a = rsqrtf(var + BN_EPS) * g[c];
        st[2 * COUT + c] = a;
        st[3 * COUT + c] = b[c] - mu * a;
    }
}

template <int COUT>
__global__ void bn_apply_relu(float* __restrict__ x, int total4,
                              const float* __restrict__ st) {
    int i = blockIdx.x * blockDim.x + threadIdx.x;
    if (i >= total4) return;
    float4 v = reinterpret_cast<float4*>(x)[i];
    int c0 = (i * 4) & (COUT - 1);
    const float* A = st + 2 * COUT;
    const float* D = st + 3 * COUT;
    v.x = fmaxf(fmaf(v.x, A[c0 + 0], D[c0 + 0]), 0.f);
    v.y = fmaxf(fmaf(v.y, A[c0 + 1], D[c0 + 1]), 0.f);
    v.z = fmaxf(fmaf(v.z, A[c0 + 2], D[c0 + 2]), 0.f);
    v.w = fmaxf(fmaf(v.w, A[c0 + 3], D[c0 + 3]), 0.f);
    reinterpret_cast<float4*>(x)[i] = v;
}

// ---------------- launch ----------------
extern "C" void kernel_launch(void* const* d_in, const int* in_sizes, int n_in,
                              void* d_out, int out_size) {
    const float* feats = (const float*)d_in[0];
    const float* W1 = (const float*)d_in[1];
    const float* W2 = (const float*)d_in[2];
    const float* W3 = (const float*)d_in[3];
    const float* g1 = (const float*)d_in[4];
    const float* b1 = (const float*)d_in[5];
    const float* g2 = (const float*)d_in[6];
    const float* b2 = (const float*)d_in[7];
    const float* g3 = (const float*)d_in[8];
    const float* b3 = (const float*)d_in[9];
    const int* rb1i = (const int*)d_in[10];
    const int* rb1o = (const int*)d_in[11];
    const int* rb2i = (const int*)d_in[12];
    const int* rb2o = (const int*)d_in[13];
    const int* rb3i = (const int*)d_in[14];
    const int* rb3o = (const int*)d_in[15];

    const int N = in_sizes[0] / 64;
    const int M = out_size / 128;
    const int P1 = in_sizes[10] / 27;
    const int P2 = in_sizes[12] / 27;
    const int P3 = in_sizes[14] / 27;

    float *x1, *x2, *st;
    cudaGetSymbolAddress((void**)&x1, g_x1);
    cudaGetSymbolAddress((void**)&x2, g_x2);
    cudaGetSymbolAddress((void**)&st, g_stats);
    float* out = (float*)d_out;

    // dynamic smem: (128 + COUT) * (2*CIN+8) bf16
    const int smem1 = (128 + 64) * (2 * 64 + 8) * 2;    // 52224
    const int smem2 = (128 + 128) * (2 * 64 + 8) * 2;   // 69632
    const int smem3 = (128 + 128) * (2 * 128 + 8) * 2;  // 135168
    cudaFuncSetAttribute(conv_mma<64, 64, 1>, cudaFuncAttributeMaxDynamicSharedMemorySize, smem1);
    cudaFuncSetAttribute(conv_mma<64, 128, 1>, cudaFuncAttributeMaxDynamicSharedMemorySize, smem2);
    cudaFuncSetAttribute(conv_mma<128, 128, 2>, cudaFuncAttributeMaxDynamicSharedMemorySize, smem3);

    // ---- stage 1: submanifold conv (N x 64) ----
    cudaMemsetAsync(x1, 0, (size_t)N * 64 * sizeof(float), 0);
    conv_mma<64, 64, 1><<<dim3(64, 27), 256, smem1, 0>>>(feats, W1, rb1i, rb1o, x1, P1, N);
    cudaMemsetAsync(st, 0, 512 * sizeof(float), 0);
    bn_stats<64><<<148, 256, 0, 0>>>(x1, N, st);
    bn_finalize<64><<<1, 64, 0, 0>>>(g1, b1, 1.f / (float)N, st);
    {
        int tot4 = N * 64 / 4;
        bn_apply_relu<64><<<(tot4 + 255) / 256, 256, 0, 0>>>(x1, tot4, st);
    }

    // ---- stage 2: stride-2 conv (M x 128) ----
    cudaMemsetAsync(x2, 0, (size_t)M * 128 * sizeof(float), 0);
    conv_mma<64, 128, 1><<<dim3(32, 27), 256, smem2, 0>>>(x1, W2, rb2i, rb2o, x2, P2, N);
    cudaMemsetAsync(st, 0, 512 * sizeof(float), 0);
    bn_stats<128><<<148, 256, 0, 0>>>(x2, M, st);
    bn_finalize<128><<<1, 128, 0, 0>>>(g2, b2, 1.f / (float)M, st);
    {
        int tot4 = M * 128 / 4;
        bn_apply_relu<128><<<(tot4 + 255) / 256, 256, 0, 0>>>(x2, tot4, st);
    }

    // ---- stage 3: submanifold conv on 32^3 grid (M x 128) -> d_out ----
    cudaMemsetAsync(out, 0, (size_t)M * 128 * sizeof(float), 0);
    conv_mma<128, 128, 2><<<dim3(48, 27), 512, smem3, 0>>>(x2, W3, rb3i, rb3o, out, P3, M);
    cudaMemsetAsync(st, 0, 512 * sizeof(float), 0);
    bn_stats<128><<<148, 256, 0, 0>>>(out, M, st);
    bn_finalize<128><<<1, 128, 0, 0>>>(g3, b3, 1.f / (float)M, st);
    {
        int tot4 = M * 128 / 4;
        bn_apply_relu<128><<<(tot4 + 255) / 256, 256, 0, 0>>>(out, tot4, st);
    }
}

// round 7
// speedup vs baseline: 1.1614x; 1.1614x over previous
#include <cuda_runtime.h>
#include <cuda_bf16.h>
#include <cstdint>

#define BN_EPS 1e-5f

// ---------------- scratch (no allocations allowed) ----------------
__device__ float g_x1[200000 * 64];        // conv1 output (N x 64)
__device__ float g_x2[(32768 + 1) * 128];  // conv2 output (M x 128)
__device__ float g_stats[512];             // [sum | sumsq | a | d]

// ---------------- packed f32x2 helpers ----------------
static __device__ __forceinline__ unsigned long long pack2(float x) {
    unsigned long long r;
    asm("mov.b64 %0, {%1, %1};" : "=l"(r) : "f"(x));
    return r;
}
static __device__ __forceinline__ void fma2(unsigned long long& acc,
                                            unsigned long long a,
                                            unsigned long long b) {
    asm("fma.rn.f32x2 %0, %1, %2, %0;" : "+l"(acc) : "l"(a), "l"(b));
}
static __device__ __forceinline__ float lo32(unsigned long long v) {
    return __uint_as_float((unsigned)v);
}
static __device__ __forceinline__ float hi32(unsigned long long v) {
    return __uint_as_float((unsigned)(v >> 32));
}
static __device__ __forceinline__ void red_add2(float* p, float a, float b) {
    asm volatile("red.global.add.v2.f32 [%0], {%1,%2};"
                 :: "l"(p), "f"(a), "f"(b) : "memory");
}

// ============================================================================
// Sparse conv, fp32 FFMA2 path. Grid (X, 27); block NTHR (128 or 256).
// Tile = 128 pairs. Warp = 32 pairs x 64 couts: p0=(wid&3)*32, c0=(wid>>2)*64.
// A smem [CIN][132] (transposed, pair-packed); W smem [CIN][COUT].
// Inner loop: A via broadcast LDS.128 (lane-uniform), W float2 per lane,
// 32 FFMA2/cin/warp -> crossbar ~63%, fma pipe binding.
// BNIN: fuse BN-apply+ReLU of the previous stage into the gather.
// Pad rows (rin==n_in, trailing) gather row 0 and never scatter.
// ============================================================================
template <int CIN, int COUT, int NTHR, bool BNIN>
__global__ __launch_bounds__(NTHR, (NTHR == 128) ? 4 : ((CIN == 64) ? 2 : 1))
void conv_ffma(const float* __restrict__ fin, const float* __restrict__ W,
               const int* __restrict__ rin, const int* __restrict__ rout,
               float* __restrict__ out, int P, int n_in,
               const float* __restrict__ bnA, const float* __restrict__ bnD) {
    constexpr int ASTR = 132;               // pair-dim stride (floats)
    constexpr int TPR = NTHR / 128;         // gather threads per pair row
    constexpr int CHUNK = CIN / TPR;

    extern __shared__ float sm[];
    float* As = sm;                          // CIN * ASTR
    float* Ws = sm + CIN * ASTR;             // CIN * COUT
    __shared__ int s_in[128], s_out[128];

    const int tid = threadIdx.x;
    const int k = blockIdx.y;
    const int rbase = k * P;
    // liveness probe: pads trail; first tile dead => all this block's tiles dead
    if ((blockIdx.x << 7) >= P) return;
    if (rin[rbase + (blockIdx.x << 7)] == n_in) return;

    // ---- cache W_k (fp32) ----
    {
        const float4* wg = (const float4*)(W + (size_t)k * CIN * COUT);
        float4* wd = (float4*)Ws;
        for (int i = tid; i < CIN * COUT / 4; i += NTHR) wd[i] = wg[i];
    }

    const int lane = tid & 31, wid = tid >> 5;
    const int p0 = (wid & 3) * 32;          // warp's 32 pairs
    const int c0 = (wid >> 2) * 64;         // warp's cout column
    const int ntiles = (P + 127) >> 7;

    for (int t = blockIdx.x; t < ntiles; t += gridDim.x) {
        if (tid < 128) {
            int idx = (t << 7) + tid;
            s_in[tid] = (idx < P) ? rin[rbase + idx] : n_in;
            s_out[tid] = (idx < P) ? rout[rbase + idx] : 0;
        }
        __syncthreads();
        if (s_in[0] == n_in) break;

        // ---- gather (+ fused BN/ReLU of previous stage), transpose to As ----
        {
            int row, cbase;
            if (TPR == 1) { row = tid; cbase = 0; }
            else          { row = tid >> 1; cbase = (tid & 1) * CHUNK; }
            int src = s_in[row];
            if (src == n_in) src = 0;       // pad row: content irrelevant
            const float4* sp = (const float4*)(fin + (size_t)src * CIN + cbase);
#pragma unroll
            for (int j = 0; j < CHUNK / 4; j++) {
                float4 v = sp[j];
                if (BNIN) {
                    float4 a4 = *(const float4*)(bnA + cbase + 4 * j);
                    float4 d4 = *(const float4*)(bnD + cbase + 4 * j);
                    v.x = fmaxf(fmaf(v.x, a4.x, d4.x), 0.f);
                    v.y = fmaxf(fmaf(v.y, a4.y, d4.y), 0.f);
                    v.z = fmaxf(fmaf(v.z, a4.z, d4.z), 0.f);
                    v.w = fmaxf(fmaf(v.w, a4.w, d4.w), 0.f);
                }
                int c = cbase + 4 * j;
                As[(c + 0) * ASTR + row] = v.x;
                As[(c + 1) * ASTR + row] = v.y;
                As[(c + 2) * ASTR + row] = v.z;
                As[(c + 3) * ASTR + row] = v.w;
            }
        }
        __syncthreads();

        // ---- GEMM: 32 pairs x 64 couts per warp, packed f32x2 ----
        unsigned long long acc[16][2];
#pragma unroll
        for (int i = 0; i < 16; i++) { acc[i][0] = 0ull; acc[i][1] = 0ull; }

#pragma unroll 2
        for (int cin = 0; cin < CIN; cin++) {
            float2 wv = *(const float2*)(Ws + cin * COUT + c0 + lane * 2);
            unsigned long long w0 = pack2(wv.x), w1 = pack2(wv.y);
            const ulonglong2* ar = (const ulonglong2*)(As + cin * ASTR + p0);
#pragma unroll
            for (int h = 0; h < 4; h++) {
                ulonglong2 aa = ar[2 * h];
                ulonglong2 bb = ar[2 * h + 1];
                fma2(acc[4 * h + 0][0], aa.x, w0); fma2(acc[4 * h + 0][1], aa.x, w1);
                fma2(acc[4 * h + 1][0], aa.y, w0); fma2(acc[4 * h + 1][1], aa.y, w1);
                fma2(acc[4 * h + 2][0], bb.x, w0); fma2(acc[4 * h + 2][1], bb.x, w1);
                fma2(acc[4 * h + 3][0], bb.y, w0); fma2(acc[4 * h + 3][1], bb.y, w1);
            }
        }

        // ---- scatter: acc[i] holds pairs (p0+2i, p0+2i+1), couts c0+lane*2(+1)
#pragma unroll
        for (int i = 0; i < 16; i++) {
            int pr = p0 + 2 * i;
            if (s_in[pr] != n_in)
                red_add2(out + (size_t)s_out[pr] * COUT + c0 + lane * 2,
                         lo32(acc[i][0]), lo32(acc[i][1]));
            if (s_in[pr + 1] != n_in)
                red_add2(out + (size_t)s_out[pr + 1] * COUT + c0 + lane * 2,
                         hi32(acc[i][0]), hi32(acc[i][1]));
        }
        __syncthreads();
    }
}

// ---------------- BatchNorm (training stats) + ReLU ----------------
template <int COUT>
__global__ void bn_stats(const float* __restrict__ x, int R, float* __restrict__ st) {
    __shared__ float ss[COUT], sq[COUT];
    int tid = threadIdx.x;
    if (tid < COUT) { ss[tid] = 0.f; sq[tid] = 0.f; }
    __syncthreads();
    int c = tid & (COUT - 1);
    constexpr int RPB = 256 / COUT;
    float s = 0.f, qq = 0.f;
    for (int r = blockIdx.x * RPB + tid / COUT; r < R; r += gridDim.x * RPB) {
        float v = x[(size_t)r * COUT + c];
        s += v;
        qq += v * v;
    }
    atomicAdd(&ss[c], s);
    atomicAdd(&sq[c], qq);
    __syncthreads();
    if (tid < COUT) {
        atomicAdd(&st[tid], ss[tid]);
        atomicAdd(&st[COUT + tid], sq[tid]);
    }
}

template <int COUT>
__global__ void bn_finalize(const float* __restrict__ g, const float* __restrict__ b,
                            float invR, float* __restrict__ st) {
    int c = threadIdx.x;
    if (c < COUT) {
        float mu = st[c] * invR;
        float var = st[COUT + c] * invR - mu * mu;
        float a = rsqrtf(var + BN_EPS) * g[c];
        st[2 * COUT + c] = a;
        st[3 * COUT + c] = b[c] - mu * a;
    }
}

template <int COUT>
__global__ void bn_apply_relu(float* __restrict__ x, int total4,
                              const float* __restrict__ st) {
    int i = blockIdx.x * blockDim.x + threadIdx.x;
    if (i >= total4) return;
    float4 v = reinterpret_cast<float4*>(x)[i];
    int c0 = (i * 4) & (COUT - 1);
    const float* A = st + 2 * COUT;
    const float* D = st + 3 * COUT;
    v.x = fmaxf(fmaf(v.x, A[c0 + 0], D[c0 + 0]), 0.f);
    v.y = fmaxf(fmaf(v.y, A[c0 + 1], D[c0 + 1]), 0.f);
    v.z = fmaxf(fmaf(v.z, A[c0 + 2], D[c0 + 2]), 0.f);
    v.w = fmaxf(fmaf(v.w, A[c0 + 3], D[c0 + 3]), 0.f);
    reinterpret_cast<float4*>(x)[i] = v;
}

// ---------------- launch ----------------
extern "C" void kernel_launch(void* const* d_in, const int* in_sizes, int n_in,
                              void* d_out, int out_size) {
    const float* feats = (const float*)d_in[0];
    const float* W1 = (const float*)d_in[1];
    const float* W2 = (const float*)d_in[2];
    const float* W3 = (const float*)d_in[3];
    const float* g1 = (const float*)d_in[4];
    const float* b1 = (const float*)d_in[5];
    const float* g2 = (const float*)d_in[6];
    const float* b2 = (const float*)d_in[7];
    const float* g3 = (const float*)d_in[8];
    const float* b3 = (const float*)d_in[9];
    const int* rb1i = (const int*)d_in[10];
    const int* rb1o = (const int*)d_in[11];
    const int* rb2i = (const int*)d_in[12];
    const int* rb2o = (const int*)d_in[13];
    const int* rb3i = (const int*)d_in[14];
    const int* rb3o = (const int*)d_in[15];

    const int N = in_sizes[0] / 64;
    const int M = out_size / 128;
    const int P1 = in_sizes[10] / 27;
    const int P2 = in_sizes[12] / 27;
    const int P3 = in_sizes[14] / 27;

    float *x1, *x2, *st;
    cudaGetSymbolAddress((void**)&x1, g_x1);
    cudaGetSymbolAddress((void**)&x2, g_x2);
    cudaGetSymbolAddress((void**)&st, g_stats);
    float* out = (float*)d_out;

    const int smem1 = (64 * 132 + 64 * 64) * 4;     // 50176
    const int smem2 = (64 * 132 + 64 * 128) * 4;    // 66560
    const int smem3 = (128 * 132 + 128 * 128) * 4;  // 133120
    cudaFuncSetAttribute((const void*)conv_ffma<64, 64, 128, false>,
                         cudaFuncAttributeMaxDynamicSharedMemorySize, smem1);
    cudaFuncSetAttribute((const void*)conv_ffma<64, 128, 256, true>,
                         cudaFuncAttributeMaxDynamicSharedMemorySize, smem2);
    cudaFuncSetAttribute((const void*)conv_ffma<128, 128, 256, true>,
                         cudaFuncAttributeMaxDynamicSharedMemorySize, smem3);

    // ---- stage 1: submanifold conv (N x 64), raw input ----
    cudaMemsetAsync(x1, 0, (size_t)N * 64 * sizeof(float), 0);
    conv_ffma<64, 64, 128, false><<<dim3(96, 27), 128, smem1, 0>>>(
        feats, W1, rb1i, rb1o, x1, P1, N, nullptr, nullptr);
    cudaMemsetAsync(st, 0, 512 * sizeof(float), 0);
    bn_stats<64><<<148, 256, 0, 0>>>(x1, N, st);
    bn_finalize<64><<<1, 64, 0, 0>>>(g1, b1, 1.f / (float)N, st);
    // BN1 apply+ReLU fused into conv2 gather (a at st+128, d at st+192)

    // ---- stage 2: stride-2 conv (M x 128), gathers BN1(x1) ----
    cudaMemsetAsync(x2, 0, (size_t)M * 128 * sizeof(float), 0);
    conv_ffma<64, 128, 256, true><<<dim3(64, 27), 256, smem2, 0>>>(
        x1, W2, rb2i, rb2o, x2, P2, N, st + 128, st + 192);
    cudaMemsetAsync(st, 0, 512 * sizeof(float), 0);
    bn_stats<128><<<148, 256, 0, 0>>>(x2, M, st);
    bn_finalize<128><<<1, 128, 0, 0>>>(g2, b2, 1.f / (float)M, st);
    // BN2 apply+ReLU fused into conv3 gather (a at st+256, d at st+384)

    // ---- stage 3: submanifold conv (M x 128) -> d_out, gathers BN2(x2) ----
    cudaMemsetAsync(out, 0, (size_t)M * 128 * sizeof(float), 0);
    conv_ffma<128, 128, 256, true><<<dim3(64, 27), 256, smem3, 0>>>(
        x2, W3, rb3i, rb3o, out, P3, M, st + 256, st + 384);
    cudaMemsetAsync(st, 0, 512 * sizeof(float), 0);
    bn_stats<128><<<148, 256, 0, 0>>>(out, M, st);
    bn_finalize<128><<<1, 128, 0, 0>>>(g3, b3, 1.f / (float)M, st);
    {
        int tot4 = M * 128 / 4;
        bn_apply_relu<128><<<(tot4 + 255) / 256, 256, 0, 0>>>(out, tot4, st);
    }
}